// round 16
// baseline (speedup 1.0000x reference)
#include <cuda_runtime.h>
#include <cuda_fp16.h>
#include <cuda_bf16.h>
#include <cstdint>

// Problem constants
#define BATCH 256
#define TLEN  512
#define DDIM  256
#define NROWS (BATCH * TLEN)

// GEMM tiling: fp16 m16n8k16, K-chunks of 64, persistent CTAs, W resident
#define BM 128
#define BN 256
#define BKH 64
#define NTHREADS 512
#define NTILES (NROWS / BM)          // 1024
#define GRID_SCORES 148

// smem layout (dynamic), bytes
#define SB_SLAB  (BN * 128)                  // 32768 per W k-slab
#define OFF_B    0                           // 4 slabs = 131072
#define SA_TILE  (BM * 128)                  // 16384
#define OFF_A    (4 * SB_SLAB)               // 131072 (A dbuf 32768)
#define OFF_SPART (OFF_A + 2 * SA_TILE)      // 163840
#define SMEM_BYTES (OFF_SPART + 16 * 64 * 4) // 167936

// scratch (static device arrays: no allocation)
__device__ float g_scores[NROWS];

__device__ __forceinline__ void ldsm_x4(unsigned r[4], unsigned addr) {
    asm volatile(
        "ldmatrix.sync.aligned.m8n8.x4.shared.b16 {%0,%1,%2,%3}, [%4];"
        : "=r"(r[0]), "=r"(r[1]), "=r"(r[2]), "=r"(r[3]) : "r"(addr));
}
__device__ __forceinline__ void ldsm_x2(unsigned& r0, unsigned& r1, unsigned addr) {
    asm volatile(
        "ldmatrix.sync.aligned.m8n8.x2.shared.b16 {%0,%1}, [%2];"
        : "=r"(r0), "=r"(r1) : "r"(addr));
}

__device__ __forceinline__ void mma_f16(float c[4],
                                        unsigned a0, unsigned a1, unsigned a2, unsigned a3,
                                        unsigned b0, unsigned b1) {
    asm volatile(
        "mma.sync.aligned.m16n8k16.row.col.f32.f16.f16.f32 "
        "{%0,%1,%2,%3}, {%4,%5,%6,%7}, {%8,%9}, {%0,%1,%2,%3};\n"
        : "+f"(c[0]), "+f"(c[1]), "+f"(c[2]), "+f"(c[3])
        : "r"(a0), "r"(a1), "r"(a2), "r"(a3), "r"(b0), "r"(b1));
}

// half-scope barrier: 256 threads, named barrier 1 (half 0) or 2 (half 1)
__device__ __forceinline__ void half_bar(int h) {
    asm volatile("bar.sync %0, 256;" :: "r"(h + 1) : "memory");
}

__device__ __forceinline__ float tanh_fast(float x) {
    x = fminf(fmaxf(x, -15.f), 15.f);
    float e = __expf(2.f * x);
    return __fdividef(e - 1.f, e + 1.f);
}

__device__ __forceinline__ unsigned pack_h2(float a, float b) {
    __half2 h = __floats2half2_rn(a, b);
    return *reinterpret_cast<unsigned*>(&h);
}

// ---------------------------------------------------------------------------
// Kernel 1: persistent fused fp16 GEMM + tanh + context dot -> g_scores.
// W fp32->fp16 in prologue, resident in smem. Two decoupled 256-thread
// halves (rows 0-63 / 64-127) synced by named barriers only.
// (Byte-identical to the proven best version — do not modify.)
// ---------------------------------------------------------------------------
__global__ void __launch_bounds__(NTHREADS, 1) scores_kernel(
    const float* __restrict__ ip,    // [NROWS, 256]
    const float* __restrict__ W,     // [256, 256] fp32
    const float* __restrict__ bias,  // [256]
    const float* __restrict__ ctx)   // [256]
{
    extern __shared__ char smem[];
    __shared__ float sbias[BN];
    __shared__ float sctx[BN];

    const int tid   = threadIdx.x;
    const int warp  = tid >> 5;
    const int lane  = tid & 31;
    const int g     = lane >> 2;
    const int tg    = lane & 3;
    const int mhalf = warp >> 3;        // 0..1
    const int nwarp = warp & 7;         // 0..7
    const int wn    = nwarp * 32;

    if (tid < BN) { sbias[tid] = bias[tid]; sctx[tid] = ctx[tid]; }

    // LDSM lane-constant addressing (PROVEN conflict-free; do not modify)
    const int s7  = lane & 7;
    const int c0a = lane >> 4;
    const unsigned aRowOff =
        (unsigned)((mhalf * 64 + ((lane >> 3) & 1) * 8 + s7) * 128);
    const int cbm = (lane >> 3) & 1;
    const unsigned bRowOff0 = (unsigned)((wn + s7) * 128);

    const unsigned smem_base = (unsigned)__cvta_generic_to_shared(smem);

    // A conversion mapping: thread owns row (tid>>2) [half-local], quarter (tid&3)
    const int aRow = tid >> 2;
    const int aQ   = tid & 3;
    const int aChunk0 = (2 * aQ) ^ (aRow & 7);
    const int aChunk1 = (2 * aQ + 1) ^ (aRow & 7);

    const int my_ntiles = (NTILES - blockIdx.x + gridDim.x - 1) / gridDim.x;
    const int total = my_ntiles * 4;     // chunk-steps

    auto aSrcFor = [&](int q) -> const float* {
        int tile = blockIdx.x + (q >> 2) * (int)gridDim.x;
        return ip + ((size_t)tile * BM + aRow) * DDIM + aQ * 16 + (q & 3) * BKH;
    };

    // prefetch A(0) first (DRAM latency overlaps with W conversion below)
    float4 areg[4];
    {
        const float* p = aSrcFor(0);
#pragma unroll
        for (int i = 0; i < 4; i++) areg[i] = *(const float4*)(p + i * 4);
    }

    // W fp32 -> fp16 swizzled resident slabs
#pragma unroll
    for (int i = 0; i < 16; i++) {
        int f = tid + i * NTHREADS;
        int slab = f >> 11;
        int rem  = f & 2047;
        int r = rem >> 3, cc = rem & 7;
        const float* src = W + r * DDIM + slab * 64 + cc * 8;
        float4 v0 = *(const float4*)(src);
        float4 v1 = *(const float4*)(src + 4);
        uint4 u;
        u.x = pack_h2(v0.x, v0.y);
        u.y = pack_h2(v0.z, v0.w);
        u.z = pack_h2(v1.x, v1.y);
        u.w = pack_h2(v1.z, v1.w);
        *(uint4*)(smem + OFF_B + slab * SB_SLAB + r * 128
                  + ((cc ^ (r & 7)) << 4)) = u;
    }
    __syncthreads();   // only full-block barrier: W visible to everyone

    float acc[4][4][4];
#pragma unroll
    for (int mt = 0; mt < 4; mt++)
#pragma unroll
        for (int nt = 0; nt < 4; nt++)
#pragma unroll
            for (int i = 0; i < 4; i++) acc[mt][nt][i] = 0.f;

    for (int q = 0; q < total; q++) {
        // STS A(q) fp16 swizzled into buffer q&1 (half-local rows)
        {
            char* dst = smem + OFF_A + (q & 1) * SA_TILE + aRow * 128;
            uint4 u0, u1;
            u0.x = pack_h2(areg[0].x, areg[0].y);
            u0.y = pack_h2(areg[0].z, areg[0].w);
            u0.z = pack_h2(areg[1].x, areg[1].y);
            u0.w = pack_h2(areg[1].z, areg[1].w);
            u1.x = pack_h2(areg[2].x, areg[2].y);
            u1.y = pack_h2(areg[2].z, areg[2].w);
            u1.z = pack_h2(areg[3].x, areg[3].y);
            u1.w = pack_h2(areg[3].z, areg[3].w);
            *(uint4*)(dst + aChunk0 * 16) = u0;
            *(uint4*)(dst + aChunk1 * 16) = u1;
        }

        // prefetch A(q+1) before the barrier
        if (q + 1 < total) {
            const float* p = aSrcFor(q + 1);
#pragma unroll
            for (int i = 0; i < 4; i++) areg[i] = *(const float4*)(p + i * 4);
        }
        half_bar(mhalf);   // half's A rows visible; half's prev buffer reusable

        const unsigned sAu = smem_base + OFF_A + (unsigned)((q & 1) * SA_TILE);
        const unsigned sBu = smem_base + OFF_B + (unsigned)((q & 3) * SB_SLAB);

#pragma unroll
        for (int ks = 0; ks < 4; ks++) {
            const int kc = ks * 2;
            unsigned a[4][4];
#pragma unroll
            for (int mt = 0; mt < 4; mt++) {
                unsigned addr = sAu + aRowOff + (unsigned)(mt * 2048)
                              + (unsigned)(((kc + c0a) ^ s7) << 4);
                ldsm_x4(a[mt], addr);
            }
#pragma unroll
            for (int nt = 0; nt < 4; nt++) {
                unsigned addr = sBu + bRowOff0 + (unsigned)(nt * 8 * 128)
                              + (unsigned)(((kc + cbm) ^ s7) << 4);
                unsigned b0, b1;
                ldsm_x2(b0, b1, addr);
#pragma unroll
                for (int mt = 0; mt < 4; mt++)
                    mma_f16(acc[mt][nt], a[mt][0], a[mt][1], a[mt][2], a[mt][3], b0, b1);
            }
        }

        if ((q & 3) == 3) {
            // ---- tile epilogue (half-local) ----
            const int tile = blockIdx.x + (q >> 2) * (int)gridDim.x;
            float rs[8];
#pragma unroll
            for (int i = 0; i < 8; i++) rs[i] = 0.f;
#pragma unroll
            for (int nt = 0; nt < 4; nt++) {
                int col = wn + nt * 8 + 2 * tg;
                float b0 = sbias[col], b1 = sbias[col + 1];
                float c0 = sctx[col],  c1 = sctx[col + 1];
#pragma unroll
                for (int mt = 0; mt < 4; mt++) {
                    rs[2 * mt]     += tanh_fast(acc[mt][nt][0] + b0) * c0
                                    + tanh_fast(acc[mt][nt][1] + b1) * c1;
                    rs[2 * mt + 1] += tanh_fast(acc[mt][nt][2] + b0) * c0
                                    + tanh_fast(acc[mt][nt][3] + b1) * c1;
                }
            }
#pragma unroll
            for (int off = 1; off <= 2; off <<= 1)
#pragma unroll
                for (int i = 0; i < 8; i++)
                    rs[i] += __shfl_xor_sync(0xffffffffu, rs[i], off);

            float* spart = (float*)(smem + OFF_SPART);   // [16 warps][64 rows]
            if (tg == 0) {
#pragma unroll
                for (int mt = 0; mt < 4; mt++) {
                    spart[warp * 64 + mt * 16 + g]     = rs[2 * mt];
                    spart[warp * 64 + mt * 16 + 8 + g] = rs[2 * mt + 1];
                }
            }
            half_bar(mhalf);
            if ((tid & 255) < 64) {
                const int lr = tid & 63;
                float s = 0.f;
#pragma unroll
                for (int w = 0; w < 8; w++)
                    s += spart[(mhalf * 8 + w) * 64 + lr];
                g_scores[(size_t)tile * BM + mhalf * 64 + lr] = s;
            }
#pragma unroll
            for (int mt = 0; mt < 4; mt++)
#pragma unroll
                for (int nt = 0; nt < 4; nt++)
#pragma unroll
                    for (int i = 0; i < 4; i++) acc[mt][nt][i] = 0.f;
        }
    }
}

// ---------------------------------------------------------------------------
// Kernel 2: softmax (no max shift: |score| <= ~10.6, exp is safe) +
// weighted sum with plain cached float4 loads. grid (BATCH, 4).
// ---------------------------------------------------------------------------
__global__ __launch_bounds__(256) void out_kernel(
    const float* __restrict__ ip, float* __restrict__ out)
{
    __shared__ float attn[TLEN];
    __shared__ float reds[8];
    __shared__ float4 sred[16][16];

    const int b  = blockIdx.x;
    const int dg = blockIdx.y * 64;
    const int tid = threadIdx.x;
    const int warp = tid >> 5;
    const int lane = tid & 31;

    const float* sc = g_scores + (size_t)b * TLEN;
    float e0 = __expf(sc[tid]);
    float e1 = __expf(sc[tid + 256]);
    attn[tid]       = e0;
    attn[tid + 256] = e1;

    float su = e0 + e1;
#pragma unroll
    for (int o = 16; o > 0; o >>= 1) su += __shfl_xor_sync(0xffffffffu, su, o);
    if (lane == 0) reds[warp] = su;
    __syncthreads();
    float tot = 0.f;
#pragma unroll
    for (int w = 0; w < 8; w++) tot += reds[w];
    float inv = 1.f / tot;

    // thread (tq, v): float4 column v of the 64-col slice, 32 t's
    const int v  = tid & 15;     // 0..15
    const int tq = tid >> 4;     // 0..15
    const int t0 = tq * 32;
    const float4* base = (const float4*)(ip + ((size_t)b * TLEN + t0) * DDIM + dg) + v;
    float4 acc = make_float4(0.f, 0.f, 0.f, 0.f);
#pragma unroll 8
    for (int t = 0; t < 32; t++) {
        float e = attn[t0 + t];
        float4 x = base[(size_t)t * (DDIM / 4)];
        acc.x = fmaf(e, x.x, acc.x);
        acc.y = fmaf(e, x.y, acc.y);
        acc.z = fmaf(e, x.z, acc.z);
        acc.w = fmaf(e, x.w, acc.w);
    }
    sred[tq][v] = acc;
    __syncthreads();

    if (tid < 64) {
        const float* sr = (const float*)sred;
        float s = 0.f;
#pragma unroll
        for (int k = 0; k < 16; k++) s += sr[k * 64 + tid];
        out[(size_t)b * DDIM + dg + tid] = s * inv;
    }
}

// ---------------------------------------------------------------------------
extern "C" void kernel_launch(void* const* d_in, const int* in_sizes, int n_in,
                              void* d_out, int out_size)
{
    const float* ip   = (const float*)d_in[0];
    const float* W    = (const float*)d_in[1];
    const float* bias = (const float*)d_in[2];
    const float* ctx  = (const float*)d_in[3];
    float* out = (float*)d_out;

    cudaFuncSetAttribute(scores_kernel,
                         cudaFuncAttributeMaxDynamicSharedMemorySize, SMEM_BYTES);

    scores_kernel<<<GRID_SCORES, NTHREADS, SMEM_BYTES>>>(ip, W, bias, ctx);
    dim3 go(BATCH, 4);
    out_kernel<<<go, 256>>>(ip, out);
}

// round 17
// speedup vs baseline: 1.0837x; 1.0837x over previous
#include <cuda_runtime.h>
#include <cuda_fp16.h>
#include <cuda_bf16.h>
#include <cstdint>

// Problem constants
#define BATCH 256
#define TLEN  512
#define DDIM  256
#define NROWS (BATCH * TLEN)

// GEMM tiling: fp16 m16n8k16, K-chunks of 64, persistent CTAs, W resident
#define BM 128
#define BN 256
#define BKH 64
#define NTHREADS 512
#define NTILES (NROWS / BM)          // 1024
#define GRID_SCORES 148

// smem layout (dynamic), bytes
#define SB_SLAB  (BN * 128)                  // 32768 per W k-slab
#define OFF_B    0                           // 4 slabs = 131072
#define SA_TILE  (BM * 128)                  // 16384
#define OFF_A    (4 * SB_SLAB)               // 131072 (A dbuf 32768)
#define OFF_SPART (OFF_A + 2 * SA_TILE)      // 163840
#define SMEM_BYTES (OFF_SPART + 16 * 64 * 4) // 167936

// scratch (static device arrays: no allocation)
__device__ float g_scores[NROWS];

__device__ __forceinline__ void ldsm_x4(unsigned r[4], unsigned addr) {
    asm volatile(
        "ldmatrix.sync.aligned.m8n8.x4.shared.b16 {%0,%1,%2,%3}, [%4];"
        : "=r"(r[0]), "=r"(r[1]), "=r"(r[2]), "=r"(r[3]) : "r"(addr));
}
__device__ __forceinline__ void ldsm_x2(unsigned& r0, unsigned& r1, unsigned addr) {
    asm volatile(
        "ldmatrix.sync.aligned.m8n8.x2.shared.b16 {%0,%1}, [%2];"
        : "=r"(r0), "=r"(r1) : "r"(addr));
}

__device__ __forceinline__ void mma_f16(float c[4],
                                        unsigned a0, unsigned a1, unsigned a2, unsigned a3,
                                        unsigned b0, unsigned b1) {
    asm volatile(
        "mma.sync.aligned.m16n8k16.row.col.f32.f16.f16.f32 "
        "{%0,%1,%2,%3}, {%4,%5,%6,%7}, {%8,%9}, {%0,%1,%2,%3};\n"
        : "+f"(c[0]), "+f"(c[1]), "+f"(c[2]), "+f"(c[3])
        : "r"(a0), "r"(a1), "r"(a2), "r"(a3), "r"(b0), "r"(b1));
}

// half-scope barrier: 256 threads, named barrier 1 (half 0) or 2 (half 1)
__device__ __forceinline__ void half_bar(int h) {
    asm volatile("bar.sync %0, 256;" :: "r"(h + 1) : "memory");
}

// HW tanh (sm_75+): single MUFU op, abs err ~1e-5 — replaces exp+div+clamps
__device__ __forceinline__ float tanh_hw(float x) {
    float y;
    asm("tanh.approx.f32 %0, %1;" : "=f"(y) : "f"(x));
    return y;
}

__device__ __forceinline__ unsigned pack_h2(float a, float b) {
    __half2 h = __floats2half2_rn(a, b);
    return *reinterpret_cast<unsigned*>(&h);
}

// ---------------------------------------------------------------------------
// Kernel 1: persistent fused fp16 GEMM + tanh + context dot -> g_scores.
// W fp32->fp16 in prologue, resident in smem. Two decoupled 256-thread
// halves (rows 0-63 / 64-127) synced by named barriers only.
// (Mainloop/addressing byte-identical to the proven best; only the
//  epilogue tanh is swapped to the HW MUFU instruction.)
// ---------------------------------------------------------------------------
__global__ void __launch_bounds__(NTHREADS, 1) scores_kernel(
    const float* __restrict__ ip,    // [NROWS, 256]
    const float* __restrict__ W,     // [256, 256] fp32
    const float* __restrict__ bias,  // [256]
    const float* __restrict__ ctx)   // [256]
{
    extern __shared__ char smem[];
    __shared__ float sbias[BN];
    __shared__ float sctx[BN];

    const int tid   = threadIdx.x;
    const int warp  = tid >> 5;
    const int lane  = tid & 31;
    const int g     = lane >> 2;
    const int tg    = lane & 3;
    const int mhalf = warp >> 3;        // 0..1
    const int nwarp = warp & 7;         // 0..7
    const int wn    = nwarp * 32;

    if (tid < BN) { sbias[tid] = bias[tid]; sctx[tid] = ctx[tid]; }

    // LDSM lane-constant addressing (PROVEN conflict-free; do not modify)
    const int s7  = lane & 7;
    const int c0a = lane >> 4;
    const unsigned aRowOff =
        (unsigned)((mhalf * 64 + ((lane >> 3) & 1) * 8 + s7) * 128);
    const int cbm = (lane >> 3) & 1;
    const unsigned bRowOff0 = (unsigned)((wn + s7) * 128);

    const unsigned smem_base = (unsigned)__cvta_generic_to_shared(smem);

    // A conversion mapping: thread owns row (tid>>2) [half-local], quarter (tid&3)
    const int aRow = tid >> 2;
    const int aQ   = tid & 3;
    const int aChunk0 = (2 * aQ) ^ (aRow & 7);
    const int aChunk1 = (2 * aQ + 1) ^ (aRow & 7);

    const int my_ntiles = (NTILES - blockIdx.x + gridDim.x - 1) / gridDim.x;
    const int total = my_ntiles * 4;     // chunk-steps

    auto aSrcFor = [&](int q) -> const float* {
        int tile = blockIdx.x + (q >> 2) * (int)gridDim.x;
        return ip + ((size_t)tile * BM + aRow) * DDIM + aQ * 16 + (q & 3) * BKH;
    };

    // prefetch A(0) first (DRAM latency overlaps with W conversion below)
    float4 areg[4];
    {
        const float* p = aSrcFor(0);
#pragma unroll
        for (int i = 0; i < 4; i++) areg[i] = *(const float4*)(p + i * 4);
    }

    // W fp32 -> fp16 swizzled resident slabs
#pragma unroll
    for (int i = 0; i < 16; i++) {
        int f = tid + i * NTHREADS;
        int slab = f >> 11;
        int rem  = f & 2047;
        int r = rem >> 3, cc = rem & 7;
        const float* src = W + r * DDIM + slab * 64 + cc * 8;
        float4 v0 = *(const float4*)(src);
        float4 v1 = *(const float4*)(src + 4);
        uint4 u;
        u.x = pack_h2(v0.x, v0.y);
        u.y = pack_h2(v0.z, v0.w);
        u.z = pack_h2(v1.x, v1.y);
        u.w = pack_h2(v1.z, v1.w);
        *(uint4*)(smem + OFF_B + slab * SB_SLAB + r * 128
                  + ((cc ^ (r & 7)) << 4)) = u;
    }
    __syncthreads();   // only full-block barrier: W visible to everyone

    float acc[4][4][4];
#pragma unroll
    for (int mt = 0; mt < 4; mt++)
#pragma unroll
        for (int nt = 0; nt < 4; nt++)
#pragma unroll
            for (int i = 0; i < 4; i++) acc[mt][nt][i] = 0.f;

    for (int q = 0; q < total; q++) {
        // STS A(q) fp16 swizzled into buffer q&1 (half-local rows)
        {
            char* dst = smem + OFF_A + (q & 1) * SA_TILE + aRow * 128;
            uint4 u0, u1;
            u0.x = pack_h2(areg[0].x, areg[0].y);
            u0.y = pack_h2(areg[0].z, areg[0].w);
            u0.z = pack_h2(areg[1].x, areg[1].y);
            u0.w = pack_h2(areg[1].z, areg[1].w);
            u1.x = pack_h2(areg[2].x, areg[2].y);
            u1.y = pack_h2(areg[2].z, areg[2].w);
            u1.z = pack_h2(areg[3].x, areg[3].y);
            u1.w = pack_h2(areg[3].z, areg[3].w);
            *(uint4*)(dst + aChunk0 * 16) = u0;
            *(uint4*)(dst + aChunk1 * 16) = u1;
        }

        // prefetch A(q+1) before the barrier
        if (q + 1 < total) {
            const float* p = aSrcFor(q + 1);
#pragma unroll
            for (int i = 0; i < 4; i++) areg[i] = *(const float4*)(p + i * 4);
        }
        half_bar(mhalf);   // half's A rows visible; half's prev buffer reusable

        const unsigned sAu = smem_base + OFF_A + (unsigned)((q & 1) * SA_TILE);
        const unsigned sBu = smem_base + OFF_B + (unsigned)((q & 3) * SB_SLAB);

#pragma unroll
        for (int ks = 0; ks < 4; ks++) {
            const int kc = ks * 2;
            unsigned a[4][4];
#pragma unroll
            for (int mt = 0; mt < 4; mt++) {
                unsigned addr = sAu + aRowOff + (unsigned)(mt * 2048)
                              + (unsigned)(((kc + c0a) ^ s7) << 4);
                ldsm_x4(a[mt], addr);
            }
#pragma unroll
            for (int nt = 0; nt < 4; nt++) {
                unsigned addr = sBu + bRowOff0 + (unsigned)(nt * 8 * 128)
                              + (unsigned)(((kc + cbm) ^ s7) << 4);
                unsigned b0, b1;
                ldsm_x2(b0, b1, addr);
#pragma unroll
                for (int mt = 0; mt < 4; mt++)
                    mma_f16(acc[mt][nt], a[mt][0], a[mt][1], a[mt][2], a[mt][3], b0, b1);
            }
        }

        if ((q & 3) == 3) {
            // ---- tile epilogue (half-local), HW tanh ----
            const int tile = blockIdx.x + (q >> 2) * (int)gridDim.x;
            float rs[8];
#pragma unroll
            for (int i = 0; i < 8; i++) rs[i] = 0.f;
#pragma unroll
            for (int nt = 0; nt < 4; nt++) {
                int col = wn + nt * 8 + 2 * tg;
                float b0 = sbias[col], b1 = sbias[col + 1];
                float c0 = sctx[col],  c1 = sctx[col + 1];
#pragma unroll
                for (int mt = 0; mt < 4; mt++) {
                    rs[2 * mt]     += tanh_hw(acc[mt][nt][0] + b0) * c0
                                    + tanh_hw(acc[mt][nt][1] + b1) * c1;
                    rs[2 * mt + 1] += tanh_hw(acc[mt][nt][2] + b0) * c0
                                    + tanh_hw(acc[mt][nt][3] + b1) * c1;
                }
            }
#pragma unroll
            for (int off = 1; off <= 2; off <<= 1)
#pragma unroll
                for (int i = 0; i < 8; i++)
                    rs[i] += __shfl_xor_sync(0xffffffffu, rs[i], off);

            float* spart = (float*)(smem + OFF_SPART);   // [16 warps][64 rows]
            if (tg == 0) {
#pragma unroll
                for (int mt = 0; mt < 4; mt++) {
                    spart[warp * 64 + mt * 16 + g]     = rs[2 * mt];
                    spart[warp * 64 + mt * 16 + 8 + g] = rs[2 * mt + 1];
                }
            }
            half_bar(mhalf);
            if ((tid & 255) < 64) {
                const int lr = tid & 63;
                float s = 0.f;
#pragma unroll
                for (int w = 0; w < 8; w++)
                    s += spart[(mhalf * 8 + w) * 64 + lr];
                g_scores[(size_t)tile * BM + mhalf * 64 + lr] = s;
            }
#pragma unroll
            for (int mt = 0; mt < 4; mt++)
#pragma unroll
                for (int nt = 0; nt < 4; nt++)
#pragma unroll
                    for (int i = 0; i < 4; i++) acc[mt][nt][i] = 0.f;
        }
    }
}

// ---------------------------------------------------------------------------
// Kernel 2: softmax (no max shift: |score| <= ~10.6, exp is safe) +
// weighted sum with plain cached float4 loads. grid (BATCH, 4).
// ---------------------------------------------------------------------------
__global__ __launch_bounds__(256) void out_kernel(
    const float* __restrict__ ip, float* __restrict__ out)
{
    __shared__ float attn[TLEN];
    __shared__ float reds[8];
    __shared__ float4 sred[16][16];

    const int b  = blockIdx.x;
    const int dg = blockIdx.y * 64;
    const int tid = threadIdx.x;
    const int warp = tid >> 5;
    const int lane = tid & 31;

    const float* sc = g_scores + (size_t)b * TLEN;
    float e0 = __expf(sc[tid]);
    float e1 = __expf(sc[tid + 256]);
    attn[tid]       = e0;
    attn[tid + 256] = e1;

    float su = e0 + e1;
#pragma unroll
    for (int o = 16; o > 0; o >>= 1) su += __shfl_xor_sync(0xffffffffu, su, o);
    if (lane == 0) reds[warp] = su;
    __syncthreads();
    float tot = 0.f;
#pragma unroll
    for (int w = 0; w < 8; w++) tot += reds[w];
    float inv = 1.f / tot;

    // thread (tq, v): float4 column v of the 64-col slice, 32 t's
    const int v  = tid & 15;     // 0..15
    const int tq = tid >> 4;     // 0..15
    const int t0 = tq * 32;
    const float4* base = (const float4*)(ip + ((size_t)b * TLEN + t0) * DDIM + dg) + v;
    float4 acc = make_float4(0.f, 0.f, 0.f, 0.f);
#pragma unroll 8
    for (int t = 0; t < 32; t++) {
        float e = attn[t0 + t];
        float4 x = base[(size_t)t * (DDIM / 4)];
        acc.x = fmaf(e, x.x, acc.x);
        acc.y = fmaf(e, x.y, acc.y);
        acc.z = fmaf(e, x.z, acc.z);
        acc.w = fmaf(e, x.w, acc.w);
    }
    sred[tq][v] = acc;
    __syncthreads();

    if (tid < 64) {
        const float* sr = (const float*)sred;
        float s = 0.f;
#pragma unroll
        for (int k = 0; k < 16; k++) s += sr[k * 64 + tid];
        out[(size_t)b * DDIM + dg + tid] = s * inv;
    }
}

// ---------------------------------------------------------------------------
extern "C" void kernel_launch(void* const* d_in, const int* in_sizes, int n_in,
                              void* d_out, int out_size)
{
    const float* ip   = (const float*)d_in[0];
    const float* W    = (const float*)d_in[1];
    const float* bias = (const float*)d_in[2];
    const float* ctx  = (const float*)d_in[3];
    float* out = (float*)d_out;

    cudaFuncSetAttribute(scores_kernel,
                         cudaFuncAttributeMaxDynamicSharedMemorySize, SMEM_BYTES);

    scores_kernel<<<GRID_SCORES, NTHREADS, SMEM_BYTES>>>(ip, W, bias, ctx);
    dim3 go(BATCH, 4);
    out_kernel<<<go, 256>>>(ip, out);
}